// round 13
// baseline (speedup 1.0000x reference)
#include <cuda_runtime.h>
#include <cuda_bf16.h>
#include <math.h>

#define N_NODES 50000
#define N_EDGES 800000
#define E_TOT   (N_EDGES + N_NODES)   // 850000, with self loops
#define DIM     128
#define MROWS   50048                 // N_NODES rounded up to 128
#define NTILES  (MROWS / 64)          // 782
#define SPAD    136                   // padded bf16 row stride (272B: 4-bank shift/row)
#define ABUF    (2 * 64 * SPAD)       // one A double-buffer half, in ushorts (34816 B)

// ---------------- scratch (device globals; no runtime allocation) ----------
__device__ __align__(16) float g_xl[N_NODES * DIM];
__device__ __align__(16) float g_xr[N_NODES * DIM];
__device__ __align__(16) unsigned short g_Ahi[MROWS * DIM];   // layer-2 A (pre-split)
__device__ __align__(16) unsigned short g_Alo[MROWS * DIM];
__device__ int g_cnt[N_NODES];
__device__ int g_off[N_NODES + 1];
__device__ int g_rank[N_EDGES];       // within-destination rank of each edge
__device__ int g_src[E_TOT];

// ---------------- fp32 -> bf16 hi/lo split ---------------------------------
__device__ __forceinline__ void split_bf16(float v, unsigned short& hi, unsigned short& lo) {
    __nv_bfloat16 h = __float2bfloat16(v);
    float r = v - __bfloat162float(h);
    __nv_bfloat16 l = __float2bfloat16(r);
    hi = *(unsigned short*)&h;
    lo = *(unsigned short*)&l;
}

// ---------------- hist: per-destination counts + per-edge rank --------------
__global__ void hist_kernel(const int* __restrict__ ei) {
    int e0 = (blockIdx.x * blockDim.x + threadIdx.x) * 8;
    if (e0 + 7 < N_EDGES) {
        int4 a = ((const int4*)(ei + N_EDGES))[(e0 >> 2)];
        int4 b = ((const int4*)(ei + N_EDGES))[(e0 >> 2) + 1];
        int4 ra, rb;
        ra.x = atomicAdd(&g_cnt[a.x], 1);
        ra.y = atomicAdd(&g_cnt[a.y], 1);
        ra.z = atomicAdd(&g_cnt[a.z], 1);
        ra.w = atomicAdd(&g_cnt[a.w], 1);
        rb.x = atomicAdd(&g_cnt[b.x], 1);
        rb.y = atomicAdd(&g_cnt[b.y], 1);
        rb.z = atomicAdd(&g_cnt[b.z], 1);
        rb.w = atomicAdd(&g_cnt[b.w], 1);
        ((int4*)g_rank)[e0 >> 2] = ra;
        ((int4*)g_rank)[(e0 >> 2) + 1] = rb;
    } else {
#pragma unroll
        for (int j = 0; j < 8; j++) {
            int e = e0 + j;
            if (e < N_EDGES) g_rank[e] = atomicAdd(&g_cnt[ei[N_EDGES + e]], 1);
        }
    }
}

// ---------------- scan (counts + 1 self-loop each) -------------------------
__global__ void scan_kernel() {
    __shared__ int part[1024];
    const int t = threadIdx.x;
    const int CH = (N_NODES + 1023) / 1024;
    int base = t * CH;
    int s = 0;
    for (int i = 0; i < CH; i++) {
        int idx = base + i;
        if (idx < N_NODES) s += g_cnt[idx] + 1;
    }
    part[t] = s;
    __syncthreads();
    for (int off = 1; off < 1024; off <<= 1) {
        int v = (t >= off) ? part[t - off] : 0;
        __syncthreads();
        part[t] += v;
        __syncthreads();
    }
    int run = (t == 0) ? 0 : part[t - 1];
    for (int i = 0; i < CH; i++) {
        int idx = base + i;
        if (idx < N_NODES) { g_off[idx] = run; run += g_cnt[idx] + 1; }
    }
    if (t == 1023) g_off[N_NODES] = run;
}

// ---------------- scatter: atomic-free (uses recorded ranks) ----------------
__global__ void scatter_kernel(const int* __restrict__ ei) {
    int base = (blockIdx.x * blockDim.x + threadIdx.x) * 8;
    if (base + 7 < N_EDGES) {
        int4 s4  = ((const int4*)ei)[base >> 2];
        int4 s4b = ((const int4*)ei)[(base >> 2) + 1];
        int4 d4  = ((const int4*)(ei + N_EDGES))[base >> 2];
        int4 d4b = ((const int4*)(ei + N_EDGES))[(base >> 2) + 1];
        int4 r4  = ((const int4*)g_rank)[base >> 2];
        int4 r4b = ((const int4*)g_rank)[(base >> 2) + 1];
        g_src[g_off[d4.x] + r4.x] = s4.x;
        g_src[g_off[d4.y] + r4.y] = s4.y;
        g_src[g_off[d4.z] + r4.z] = s4.z;
        g_src[g_off[d4.w] + r4.w] = s4.w;
        g_src[g_off[d4b.x] + r4b.x] = s4b.x;
        g_src[g_off[d4b.y] + r4b.y] = s4b.y;
        g_src[g_off[d4b.z] + r4b.z] = s4b.z;
        g_src[g_off[d4b.w] + r4b.w] = s4b.w;
    } else {
#pragma unroll
        for (int j = 0; j < 8; j++) {
            int e = base + j;
            if (e < E_TOT) {
                if (e < N_EDGES) {
                    int d = ei[N_EDGES + e];
                    g_src[g_off[d] + g_rank[e]] = ei[e];
                } else {
                    int n = e - N_EDGES;          // self loop -> last slot of node n
                    g_src[g_off[n + 1] - 1] = n;
                }
            }
        }
    }
}

// ---------------- tensor-core GEMM: W-fused, double-buffered A -------------
// W conversion (fp32 -> bf16 hi/lo, transpose, pad) fused into the prologue:
// each CTA reads both fp32 weight matrices directly (same bytes as the bf16
// pair previously) and writes them split into resident smem.
#define MMA_B16(d, a, b)                                                        \
    asm volatile(                                                               \
        "mma.sync.aligned.m16n8k16.row.col.f32.bf16.bf16.f32 "                  \
        "{%0,%1,%2,%3},{%4,%5,%6,%7},{%8,%9},{%0,%1,%2,%3};\n"                  \
        : "+f"(d[0]), "+f"(d[1]), "+f"(d[2]), "+f"(d[3])                        \
        : "r"(a[0]), "r"(a[1]), "r"(a[2]), "r"(a[3]), "r"(b[0]), "r"(b[1]))

__device__ __forceinline__ void ldsm_x4(unsigned& r0, unsigned& r1,
                                        unsigned& r2, unsigned& r3, unsigned addr) {
    asm volatile("ldmatrix.sync.aligned.m8n8.x4.shared.b16 {%0,%1,%2,%3}, [%4];"
                 : "=r"(r0), "=r"(r1), "=r"(r2), "=r"(r3) : "r"(addr));
}

__global__ __launch_bounds__(512, 1)
void gemm_tc(const float* __restrict__ X,
             const float* __restrict__ WA, const float* __restrict__ WB,
             int presplit, float* __restrict__ C0, float* __restrict__ C1) {
    extern __shared__ unsigned short sm[];
    unsigned short* sWhi = sm;                       // 2 matrices x 128 x SPAD
    unsigned short* sWlo = sm + 2 * 128 * SPAD;
    unsigned short* sA   = sm + 4 * 128 * SPAD;      // 2 x ABUF (hi|lo per buffer)

    const int t = threadIdx.x;

    // Fused W prep: read fp32 W[k][n], split, store transposed [n][k] padded.
    // 2 matrices x 128 k-rows x 32 float4 = 8192 float4 chunks.
    for (int i = t; i < 8192; i += 512) {
        int m = i >> 12;                 // matrix
        int j = i & 4095;
        int k = j >> 5, n4 = j & 31;
        const float* W = m ? WB : WA;
        float4 v = ((const float4*)W)[k * 32 + n4];
        unsigned short* dh = sWhi + m * 128 * SPAD;
        unsigned short* dl = sWlo + m * 128 * SPAD;
        int n = n4 * 4;
        unsigned short h, l;
        split_bf16(v.x, h, l); dh[(n + 0) * SPAD + k] = h; dl[(n + 0) * SPAD + k] = l;
        split_bf16(v.y, h, l); dh[(n + 1) * SPAD + k] = h; dl[(n + 1) * SPAD + k] = l;
        split_bf16(v.z, h, l); dh[(n + 2) * SPAD + k] = h; dl[(n + 2) * SPAD + k] = l;
        split_bf16(v.w, h, l); dh[(n + 3) * SPAD + k] = h; dl[(n + 3) * SPAD + k] = l;
    }
    // zero the k-padding columns (k = 128..135) once
    for (int i = t; i < 2 * 128; i += 512) {
        int m = i >> 7, n = i & 127;
        unsigned short* dh = sWhi + m * 128 * SPAD + n * SPAD;
        unsigned short* dl = sWlo + m * 128 * SPAD + n * SPAD;
#pragma unroll
        for (int k = 128; k < SPAD; k++) { dh[k] = 0; dl[k] = 0; }
    }

    const int lane = t & 31, wid = t >> 5;
    const int half = wid >> 3, w8 = wid & 7;
    const int warpM = w8 & 1, warpN = w8 >> 1;       // 2 x 4 grid, warp tile 32x32
    const int g = lane >> 2, q = lane & 3;
    float* C = half ? C1 : C0;

    const unsigned aRow = warpM * 32 + (lane & 15);
    const unsigned aCol = (lane >> 4) * 8;
    const unsigned aHiBase0 = (unsigned)__cvta_generic_to_shared(sA) + (aRow * SPAD + aCol) * 2;
    const unsigned aLoBase0 = aHiBase0 + 64 * SPAD * 2;
    const unsigned bRow = warpN * 32 + ((lane >> 4) << 3) + (lane & 7);
    const unsigned bCol = ((lane >> 3) & 1) * 8;
    const unsigned bHiBase = (unsigned)__cvta_generic_to_shared(sWhi + half * 128 * SPAD)
                             + (bRow * SPAD + bCol) * 2;
    const unsigned bLoBase = (unsigned)__cvta_generic_to_shared(sWlo + half * 128 * SPAD)
                             + (bRow * SPAD + bCol) * 2;

    float4 pv0, pv1, pv2, pv3;
    uint4  ph0, ph1, pl0, pl1;

#define LOADA(tile)                                                             \
    do {                                                                        \
        if (presplit) {                                                         \
            const uint4* gAhi = (const uint4*)g_Ahi + (tile) * 1024;            \
            const uint4* gAlo = (const uint4*)g_Alo + (tile) * 1024;            \
            ph0 = gAhi[t];            ph1 = gAhi[t + 512];                      \
            pl0 = gAlo[t];            pl1 = gAlo[t + 512];                      \
        } else {                                                                \
            const float4* gX = (const float4*)X;                                \
            int r0_ = (tile) * 64;                                              \
            int row0 = t >> 5, c4 = t & 31;                                     \
            float4 z = make_float4(0.f, 0.f, 0.f, 0.f);                         \
            int gr;                                                             \
            gr = r0_ + row0;      pv0 = (gr < N_NODES) ? gX[gr * 32 + c4] : z;  \
            gr = r0_ + row0 + 16; pv1 = (gr < N_NODES) ? gX[gr * 32 + c4] : z;  \
            gr = r0_ + row0 + 32; pv2 = (gr < N_NODES) ? gX[gr * 32 + c4] : z;  \
            gr = r0_ + row0 + 48; pv3 = (gr < N_NODES) ? gX[gr * 32 + c4] : z;  \
        }                                                                       \
    } while (0)

#define STOREA(p_)                                                              \
    do {                                                                        \
        unsigned short* bhi = sA + (p_) * ABUF;                                 \
        unsigned short* blo = bhi + 64 * SPAD;                                  \
        if (presplit) {                                                         \
            int row = t >> 4, c = t & 15;                                       \
            ((uint4*)bhi)[row * 17 + c] = ph0;                                  \
            ((uint4*)blo)[row * 17 + c] = pl0;                                  \
            ((uint4*)bhi)[(row + 32) * 17 + c] = ph1;                           \
            ((uint4*)blo)[(row + 32) * 17 + c] = pl1;                           \
        } else {                                                                \
            int row = t >> 5, c4 = t & 31;                                      \
            ushort4 h, l;                                                       \
            split_bf16(pv0.x, h.x, l.x); split_bf16(pv0.y, h.y, l.y);           \
            split_bf16(pv0.z, h.z, l.z); split_bf16(pv0.w, h.w, l.w);           \
            ((ushort4*)bhi)[row * 34 + c4] = h;                                 \
            ((ushort4*)blo)[row * 34 + c4] = l;                                 \
            split_bf16(pv1.x, h.x, l.x); split_bf16(pv1.y, h.y, l.y);           \
            split_bf16(pv1.z, h.z, l.z); split_bf16(pv1.w, h.w, l.w);           \
            ((ushort4*)bhi)[(row + 16) * 34 + c4] = h;                          \
            ((ushort4*)blo)[(row + 16) * 34 + c4] = l;                          \
            split_bf16(pv2.x, h.x, l.x); split_bf16(pv2.y, h.y, l.y);           \
            split_bf16(pv2.z, h.z, l.z); split_bf16(pv2.w, h.w, l.w);           \
            ((ushort4*)bhi)[(row + 32) * 34 + c4] = h;                          \
            ((ushort4*)blo)[(row + 32) * 34 + c4] = l;                          \
            split_bf16(pv3.x, h.x, l.x); split_bf16(pv3.y, h.y, l.y);           \
            split_bf16(pv3.z, h.z, l.z); split_bf16(pv3.w, h.w, l.w);           \
            ((ushort4*)bhi)[(row + 48) * 34 + c4] = h;                          \
            ((ushort4*)blo)[(row + 48) * 34 + c4] = l;                          \
        }                                                                       \
    } while (0)

    const int tile0 = blockIdx.x;
    if (tile0 < NTILES) {
        LOADA(tile0);
        STOREA(0);
    }
    __syncthreads();

    int p = 0;
    for (int tile = tile0; tile < NTILES; tile += gridDim.x) {
        const int nxt = tile + gridDim.x;
        if (nxt < NTILES) LOADA(nxt);

        const unsigned aOff = p * ABUF * 2;
        float acc[2][4][4];
#pragma unroll
        for (int mi = 0; mi < 2; mi++)
#pragma unroll
            for (int ni = 0; ni < 4; ni++)
#pragma unroll
                for (int j = 0; j < 4; j++) acc[mi][ni][j] = 0.f;

#pragma unroll
        for (int k0 = 0; k0 < 128; k0 += 16) {
            unsigned a_hi[2][4], a_lo[2][4];
#pragma unroll
            for (int mi = 0; mi < 2; mi++) {
                unsigned off = mi * 16 * SPAD * 2 + k0 * 2 + aOff;
                ldsm_x4(a_hi[mi][0], a_hi[mi][1], a_hi[mi][2], a_hi[mi][3], aHiBase0 + off);
                ldsm_x4(a_lo[mi][0], a_lo[mi][1], a_lo[mi][2], a_lo[mi][3], aLoBase0 + off);
            }
            unsigned b_hi[4][2], b_lo[4][2];
#pragma unroll
            for (int nj = 0; nj < 2; nj++) {
                unsigned off = nj * 16 * SPAD * 2 + k0 * 2;
                ldsm_x4(b_hi[2 * nj][0], b_hi[2 * nj][1],
                        b_hi[2 * nj + 1][0], b_hi[2 * nj + 1][1], bHiBase + off);
                ldsm_x4(b_lo[2 * nj][0], b_lo[2 * nj][1],
                        b_lo[2 * nj + 1][0], b_lo[2 * nj + 1][1], bLoBase + off);
            }
#pragma unroll
            for (int mi = 0; mi < 2; mi++)
#pragma unroll
                for (int ni = 0; ni < 4; ni++) {
                    MMA_B16(acc[mi][ni], a_hi[mi], b_hi[ni]);
                    MMA_B16(acc[mi][ni], a_hi[mi], b_lo[ni]);
                    MMA_B16(acc[mi][ni], a_lo[mi], b_hi[ni]);
                }
        }

        const int r0 = tile * 64;
#pragma unroll
        for (int mi = 0; mi < 2; mi++) {
            int r = r0 + warpM * 32 + mi * 16 + g;
#pragma unroll
            for (int ni = 0; ni < 4; ni++) {
                int c = warpN * 32 + ni * 8 + q * 2;
                if (r < N_NODES)
                    *(float2*)&C[r * DIM + c] = make_float2(acc[mi][ni][0], acc[mi][ni][1]);
                if (r + 8 < N_NODES)
                    *(float2*)&C[(r + 8) * DIM + c] = make_float2(acc[mi][ni][2], acc[mi][ni][3]);
            }
        }

        if (nxt < NTILES) STOREA(p ^ 1);
        __syncthreads();
        p ^= 1;
    }
#undef LOADA
#undef STOREA
}

// ---------------- GATv2 edge aggregation: one warp per dst node ------------
// Softmax without max subtraction (logits O(±7), fp32-safe).
// att*lrelu(s) = s * (s>0 ? att : 0.2*att).  8-edge unroll for MLP=8.
__device__ __forceinline__ float head_logit(float4 xv, float4 xrv,
                                            float4 av, float4 avn) {
    float s0 = xv.x + xrv.x;
    float s1 = xv.y + xrv.y;
    float s2 = xv.z + xrv.z;
    float s3 = xv.w + xrv.w;
    float p = s0 * (s0 > 0.f ? av.x : avn.x);
    p = fmaf(s1, (s1 > 0.f ? av.y : avn.y), p);
    p = fmaf(s2, (s2 > 0.f ? av.z : avn.z), p);
    p = fmaf(s3, (s3 > 0.f ? av.w : avn.w), p);
    return p;
}

// mode 0: concat + relu, output fused into bf16 hi/lo split (layer-2 A operand)
// mode 1: head-mean + relu, fp32 to `out`
__global__ __launch_bounds__(256)
void gat_edge(const float* __restrict__ xl, const float* __restrict__ xr,
              const float* __restrict__ att, const float* __restrict__ bias,
              float* __restrict__ out, int mode) {
    int warp = (blockIdx.x * blockDim.x + threadIdx.x) >> 5;
    if (warp >= N_NODES) return;
    const int lane = threadIdx.x & 31;
    const int node = warp;

    const float4 xrv = ((const float4*)xr)[node * 32 + lane];
    const float4 av  = ((const float4*)att)[lane];
    const float4 avn = make_float4(0.2f * av.x, 0.2f * av.y, 0.2f * av.z, 0.2f * av.w);

    const int beg = g_off[node];
    const int end = g_off[node + 1];

    float  dsum = 0.f;
    float4 acc = make_float4(0.f, 0.f, 0.f, 0.f);

    int e = beg;
    for (; e + 8 <= end; e += 8) {
        int ss[8];
#pragma unroll
        for (int j = 0; j < 8; j++) ss[j] = g_src[e + j];
        float4 xv[8];
#pragma unroll
        for (int j = 0; j < 8; j++) xv[j] = ((const float4*)xl)[ss[j] * 32 + lane];
        float pp[8];
#pragma unroll
        for (int j = 0; j < 8; j++) pp[j] = head_logit(xv[j], xrv, av, avn);
#pragma unroll
        for (int j = 0; j < 8; j++) pp[j] += __shfl_xor_sync(0xffffffffu, pp[j], 1);
#pragma unroll
        for (int j = 0; j < 8; j++) pp[j] += __shfl_xor_sync(0xffffffffu, pp[j], 2);
#pragma unroll
        for (int j = 0; j < 8; j++) pp[j] += __shfl_xor_sync(0xffffffffu, pp[j], 4);
#pragma unroll
        for (int j = 0; j < 8; j++) {
            float w = __expf(pp[j]);
            dsum += w;
            acc.x += w * xv[j].x;
            acc.y += w * xv[j].y;
            acc.z += w * xv[j].z;
            acc.w += w * xv[j].w;
        }
    }
    for (; e + 2 <= end; e += 2) {
        int s0 = g_src[e], s1 = g_src[e + 1];
        float4 x0 = ((const float4*)xl)[s0 * 32 + lane];
        float4 x1 = ((const float4*)xl)[s1 * 32 + lane];
        float p0 = head_logit(x0, xrv, av, avn);
        float p1 = head_logit(x1, xrv, av, avn);
        p0 += __shfl_xor_sync(0xffffffffu, p0, 1);
        p1 += __shfl_xor_sync(0xffffffffu, p1, 1);
        p0 += __shfl_xor_sync(0xffffffffu, p0, 2);
        p1 += __shfl_xor_sync(0xffffffffu, p1, 2);
        p0 += __shfl_xor_sync(0xffffffffu, p0, 4);
        p1 += __shfl_xor_sync(0xffffffffu, p1, 4);
        float w0 = __expf(p0);
        float w1 = __expf(p1);
        dsum += w0 + w1;
        acc.x += w0 * x0.x + w1 * x1.x;
        acc.y += w0 * x0.y + w1 * x1.y;
        acc.z += w0 * x0.z + w1 * x1.z;
        acc.w += w0 * x0.w + w1 * x1.w;
    }
    if (e < end) {
        int s = g_src[e];
        float4 xv = ((const float4*)xl)[s * 32 + lane];
        float p = head_logit(xv, xrv, av, avn);
        p += __shfl_xor_sync(0xffffffffu, p, 1);
        p += __shfl_xor_sync(0xffffffffu, p, 2);
        p += __shfl_xor_sync(0xffffffffu, p, 4);
        float w = __expf(p);
        dsum += w;
        acc.x += w * xv.x;
        acc.y += w * xv.y;
        acc.z += w * xv.z;
        acc.w += w * xv.w;
    }

    float inv = 1.f / dsum;
    if (mode == 0) {
        float4 b = ((const float4*)bias)[lane];
        float o0 = fmaxf(acc.x * inv + b.x, 0.f);
        float o1 = fmaxf(acc.y * inv + b.y, 0.f);
        float o2 = fmaxf(acc.z * inv + b.z, 0.f);
        float o3 = fmaxf(acc.w * inv + b.w, 0.f);
        ushort4 hv, lv;
        split_bf16(o0, hv.x, lv.x);
        split_bf16(o1, hv.y, lv.y);
        split_bf16(o2, hv.z, lv.z);
        split_bf16(o3, hv.w, lv.w);
        ((ushort4*)g_Ahi)[node * 32 + lane] = hv;
        ((ushort4*)g_Alo)[node * 32 + lane] = lv;
    } else {
        float vx = acc.x * inv, vy = acc.y * inv, vz = acc.z * inv, vw = acc.w * inv;
        vx += __shfl_xor_sync(0xffffffffu, vx, 8);
        vx += __shfl_xor_sync(0xffffffffu, vx, 16);
        vy += __shfl_xor_sync(0xffffffffu, vy, 8);
        vy += __shfl_xor_sync(0xffffffffu, vy, 16);
        vz += __shfl_xor_sync(0xffffffffu, vz, 8);
        vz += __shfl_xor_sync(0xffffffffu, vz, 16);
        vw += __shfl_xor_sync(0xffffffffu, vw, 8);
        vw += __shfl_xor_sync(0xffffffffu, vw, 16);
        if (lane < 8) {
            float4 b = ((const float4*)bias)[lane];
            float4 o;
            o.x = fmaxf(vx * 0.25f + b.x, 0.f);
            o.y = fmaxf(vy * 0.25f + b.y, 0.f);
            o.z = fmaxf(vz * 0.25f + b.z, 0.f);
            o.w = fmaxf(vw * 0.25f + b.w, 0.f);
            ((float4*)out)[node * 8 + lane] = o;
        }
    }
}

// ---------------- launch ---------------------------------------------------
// Graph fork-join: CSR build (memset->hist->scan->scatter) on a side stream,
// concurrent with gemm1 on the capture stream; joined before gat_edge1.
extern "C" void kernel_launch(void* const* d_in, const int* in_sizes, int n_in,
                              void* d_out, int out_size) {
    const float* x    = (const float*)d_in[0];
    const int*   ei   = (const int*)d_in[1];
    const float* Wl1  = (const float*)d_in[2];
    const float* Wr1  = (const float*)d_in[3];
    const float* att1 = (const float*)d_in[4];
    const float* b1   = (const float*)d_in[5];
    const float* Wl2  = (const float*)d_in[6];
    const float* Wr2  = (const float*)d_in[7];
    const float* att2 = (const float*)d_in[8];
    const float* b2   = (const float*)d_in[9];
    float* out = (float*)d_out;

    void* p_cnt = nullptr;
    float *xl = nullptr, *xr = nullptr;
    cudaGetSymbolAddress(&p_cnt, g_cnt);
    cudaGetSymbolAddress((void**)&xl, g_xl);
    cudaGetSymbolAddress((void**)&xr, g_xr);

    static cudaStream_t side = nullptr;
    static cudaEvent_t evFork = nullptr, evJoin = nullptr;
    if (side == nullptr) {
        cudaStreamCreateWithFlags(&side, cudaStreamNonBlocking);
        cudaEventCreateWithFlags(&evFork, cudaEventDisableTiming);
        cudaEventCreateWithFlags(&evJoin, cudaEventDisableTiming);
    }

    const int SMEM = (4 * 128 * SPAD + 2 * ABUF) * 2;  // 208896 bytes
    cudaFuncSetAttribute(gemm_tc, cudaFuncAttributeMaxDynamicSharedMemorySize, SMEM);

    // ---- fork: CSR build on side stream ----
    cudaEventRecord(evFork, 0);
    cudaStreamWaitEvent(side, evFork, 0);
    cudaMemsetAsync(p_cnt, 0, N_NODES * sizeof(int), side);
    hist_kernel<<<(N_EDGES + 2047) / 2048, 256, 0, side>>>(ei);
    scan_kernel<<<1, 1024, 0, side>>>();
    scatter_kernel<<<(E_TOT + 2047) / 2048, 256, 0, side>>>(ei);
    cudaEventRecord(evJoin, side);

    // ---- main: layer-1 GEMM (W conversion fused into prologue) ----
    gemm_tc<<<148, 512, SMEM>>>(x, Wl1, Wr1, 0, xl, xr);

    // ---- join, then edge phases ----
    cudaStreamWaitEvent(0, evJoin, 0);
    gat_edge<<<(N_NODES * 32 + 255) / 256, 256>>>(xl, xr, att1, b1, nullptr, 0);
    gemm_tc<<<148, 512, SMEM>>>(nullptr, Wl2, Wr2, 1, xl, xr);
    gat_edge<<<(N_NODES * 32 + 255) / 256, 256>>>(xl, xr, att2, b2, out, 1);
}

// round 14
// speedup vs baseline: 1.7278x; 1.7278x over previous
#include <cuda_runtime.h>
#include <cuda_bf16.h>
#include <math.h>

#define N_NODES 50000
#define N_EDGES 800000
#define E_TOT   (N_EDGES + N_NODES)   // 850000, with self loops
#define DIM     128
#define MROWS   50048                 // N_NODES rounded up to 128
#define NTILES  (MROWS / 64)          // 782
#define SPAD    136                   // padded bf16 row stride (272B: 4-bank shift/row)
#define ABUF    (2 * 64 * SPAD)       // one A double-buffer half, in ushorts (34816 B)

// ---------------- scratch (device globals; no runtime allocation) ----------
__device__ __align__(16) float g_xl[N_NODES * DIM];
__device__ __align__(16) float g_xr[N_NODES * DIM];
__device__ __align__(16) unsigned short g_Ahi[MROWS * DIM];   // layer-2 A (pre-split)
__device__ __align__(16) unsigned short g_Alo[MROWS * DIM];
__device__ __align__(16) unsigned short g_Wthi[4 * 128 * SPAD];  // transposed [n][k], padded
__device__ __align__(16) unsigned short g_Wtlo[4 * 128 * SPAD];
__device__ int g_cnt[N_NODES];
__device__ int g_off[N_NODES + 1];
__device__ int g_rank[N_EDGES];       // within-destination rank of each edge
__device__ int g_src[E_TOT];

// ---------------- fp32 -> bf16 hi/lo split ---------------------------------
__device__ __forceinline__ void split_bf16(float v, unsigned short& hi, unsigned short& lo) {
    __nv_bfloat16 h = __float2bfloat16(v);
    float r = v - __bfloat162float(h);
    __nv_bfloat16 l = __float2bfloat16(r);
    hi = *(unsigned short*)&h;
    lo = *(unsigned short*)&l;
}

// ---------------- prep_W: convert+transpose 4 weight matrices ---------------
__global__ void prep_W(const float* __restrict__ W0, const float* __restrict__ W1,
                       const float* __restrict__ W2, const float* __restrict__ W3) {
    int i = blockIdx.x * 256 + threadIdx.x;
    int m = i / (128 * SPAD);
    int j = i % (128 * SPAD);
    int n = j / SPAD, k = j % SPAD;
    const float* W = (m == 0) ? W0 : (m == 1) ? W1 : (m == 2) ? W2 : W3;
    float v = (k < 128) ? W[k * 128 + n] : 0.f;
    unsigned short h, l;
    split_bf16(v, h, l);
    g_Wthi[i] = h;
    g_Wtlo[i] = l;
}

// ---------------- hist: per-destination counts + per-edge rank --------------
__global__ void hist_kernel(const int* __restrict__ ei) {
    int e0 = (blockIdx.x * blockDim.x + threadIdx.x) * 8;
    if (e0 + 7 < N_EDGES) {
        int4 a = ((const int4*)(ei + N_EDGES))[(e0 >> 2)];
        int4 b = ((const int4*)(ei + N_EDGES))[(e0 >> 2) + 1];
        int4 ra, rb;
        ra.x = atomicAdd(&g_cnt[a.x], 1);
        ra.y = atomicAdd(&g_cnt[a.y], 1);
        ra.z = atomicAdd(&g_cnt[a.z], 1);
        ra.w = atomicAdd(&g_cnt[a.w], 1);
        rb.x = atomicAdd(&g_cnt[b.x], 1);
        rb.y = atomicAdd(&g_cnt[b.y], 1);
        rb.z = atomicAdd(&g_cnt[b.z], 1);
        rb.w = atomicAdd(&g_cnt[b.w], 1);
        ((int4*)g_rank)[e0 >> 2] = ra;
        ((int4*)g_rank)[(e0 >> 2) + 1] = rb;
    } else {
#pragma unroll
        for (int j = 0; j < 8; j++) {
            int e = e0 + j;
            if (e < N_EDGES) g_rank[e] = atomicAdd(&g_cnt[ei[N_EDGES + e]], 1);
        }
    }
}

// ---------------- scan (counts + 1 self-loop each) -------------------------
__global__ void scan_kernel() {
    __shared__ int part[1024];
    const int t = threadIdx.x;
    const int CH = (N_NODES + 1023) / 1024;
    int base = t * CH;
    int s = 0;
    for (int i = 0; i < CH; i++) {
        int idx = base + i;
        if (idx < N_NODES) s += g_cnt[idx] + 1;
    }
    part[t] = s;
    __syncthreads();
    for (int off = 1; off < 1024; off <<= 1) {
        int v = (t >= off) ? part[t - off] : 0;
        __syncthreads();
        part[t] += v;
        __syncthreads();
    }
    int run = (t == 0) ? 0 : part[t - 1];
    for (int i = 0; i < CH; i++) {
        int idx = base + i;
        if (idx < N_NODES) { g_off[idx] = run; run += g_cnt[idx] + 1; }
    }
    if (t == 1023) g_off[N_NODES] = run;
}

// ---------------- scatter: atomic-free (uses recorded ranks) ----------------
__global__ void scatter_kernel(const int* __restrict__ ei) {
    int base = (blockIdx.x * blockDim.x + threadIdx.x) * 8;
    if (base + 7 < N_EDGES) {
        int4 s4  = ((const int4*)ei)[base >> 2];
        int4 s4b = ((const int4*)ei)[(base >> 2) + 1];
        int4 d4  = ((const int4*)(ei + N_EDGES))[base >> 2];
        int4 d4b = ((const int4*)(ei + N_EDGES))[(base >> 2) + 1];
        int4 r4  = ((const int4*)g_rank)[base >> 2];
        int4 r4b = ((const int4*)g_rank)[(base >> 2) + 1];
        g_src[g_off[d4.x] + r4.x] = s4.x;
        g_src[g_off[d4.y] + r4.y] = s4.y;
        g_src[g_off[d4.z] + r4.z] = s4.z;
        g_src[g_off[d4.w] + r4.w] = s4.w;
        g_src[g_off[d4b.x] + r4b.x] = s4b.x;
        g_src[g_off[d4b.y] + r4b.y] = s4b.y;
        g_src[g_off[d4b.z] + r4b.z] = s4b.z;
        g_src[g_off[d4b.w] + r4b.w] = s4b.w;
    } else {
#pragma unroll
        for (int j = 0; j < 8; j++) {
            int e = base + j;
            if (e < E_TOT) {
                if (e < N_EDGES) {
                    int d = ei[N_EDGES + e];
                    g_src[g_off[d] + g_rank[e]] = ei[e];
                } else {
                    int n = e - N_EDGES;          // self loop -> last slot of node n
                    g_src[g_off[n + 1] - 1] = n;
                }
            }
        }
    }
}

// ---------------- tensor-core GEMM: W-resident, double-buffered A ----------
#define MMA_B16(d, a, b)                                                        \
    asm volatile(                                                               \
        "mma.sync.aligned.m16n8k16.row.col.f32.bf16.bf16.f32 "                  \
        "{%0,%1,%2,%3},{%4,%5,%6,%7},{%8,%9},{%0,%1,%2,%3};\n"                  \
        : "+f"(d[0]), "+f"(d[1]), "+f"(d[2]), "+f"(d[3])                        \
        : "r"(a[0]), "r"(a[1]), "r"(a[2]), "r"(a[3]), "r"(b[0]), "r"(b[1]))

__device__ __forceinline__ void ldsm_x4(unsigned& r0, unsigned& r1,
                                        unsigned& r2, unsigned& r3, unsigned addr) {
    asm volatile("ldmatrix.sync.aligned.m8n8.x4.shared.b16 {%0,%1,%2,%3}, [%4];"
                 : "=r"(r0), "=r"(r1), "=r"(r2), "=r"(r3) : "r"(addr));
}

__global__ __launch_bounds__(512, 1)
void gemm_tc(const float* __restrict__ X, int wbase, int presplit,
             float* __restrict__ C0, float* __restrict__ C1) {
    extern __shared__ unsigned short sm[];
    unsigned short* sWhi = sm;                       // 2 matrices x 128 x SPAD
    unsigned short* sWlo = sm + 2 * 128 * SPAD;
    unsigned short* sA   = sm + 4 * 128 * SPAD;      // 2 x ABUF (hi|lo per buffer)

    const int t = threadIdx.x;

    const uint4* gWhi = (const uint4*)(g_Wthi + wbase * 128 * SPAD);
    const uint4* gWlo = (const uint4*)(g_Wtlo + wbase * 128 * SPAD);
    for (int i = t; i < 4352; i += 512) {
        ((uint4*)sWhi)[i] = gWhi[i];
        ((uint4*)sWlo)[i] = gWlo[i];
    }

    const int lane = t & 31, wid = t >> 5;
    const int half = wid >> 3, w8 = wid & 7;
    const int warpM = w8 & 1, warpN = w8 >> 1;       // 2 x 4 grid, warp tile 32x32
    const int g = lane >> 2, q = lane & 3;
    float* C = half ? C1 : C0;

    const unsigned aRow = warpM * 32 + (lane & 15);
    const unsigned aCol = (lane >> 4) * 8;
    const unsigned aHiBase0 = (unsigned)__cvta_generic_to_shared(sA) + (aRow * SPAD + aCol) * 2;
    const unsigned aLoBase0 = aHiBase0 + 64 * SPAD * 2;
    const unsigned bRow = warpN * 32 + ((lane >> 4) << 3) + (lane & 7);
    const unsigned bCol = ((lane >> 3) & 1) * 8;
    const unsigned bHiBase = (unsigned)__cvta_generic_to_shared(sWhi + half * 128 * SPAD)
                             + (bRow * SPAD + bCol) * 2;
    const unsigned bLoBase = (unsigned)__cvta_generic_to_shared(sWlo + half * 128 * SPAD)
                             + (bRow * SPAD + bCol) * 2;

    float4 pv0, pv1, pv2, pv3;
    uint4  ph0, ph1, pl0, pl1;

#define LOADA(tile)                                                             \
    do {                                                                        \
        if (presplit) {                                                         \
            const uint4* gAhi = (const uint4*)g_Ahi + (tile) * 1024;            \
            const uint4* gAlo = (const uint4*)g_Alo + (tile) * 1024;            \
            ph0 = gAhi[t];            ph1 = gAhi[t + 512];                      \
            pl0 = gAlo[t];            pl1 = gAlo[t + 512];                      \
        } else {                                                                \
            const float4* gX = (const float4*)X;                                \
            int r0_ = (tile) * 64;                                              \
            int row0 = t >> 5, c4 = t & 31;                                     \
            float4 z = make_float4(0.f, 0.f, 0.f, 0.f);                         \
            int gr;                                                             \
            gr = r0_ + row0;      pv0 = (gr < N_NODES) ? gX[gr * 32 + c4] : z;  \
            gr = r0_ + row0 + 16; pv1 = (gr < N_NODES) ? gX[gr * 32 + c4] : z;  \
            gr = r0_ + row0 + 32; pv2 = (gr < N_NODES) ? gX[gr * 32 + c4] : z;  \
            gr = r0_ + row0 + 48; pv3 = (gr < N_NODES) ? gX[gr * 32 + c4] : z;  \
        }                                                                       \
    } while (0)

#define STOREA(p_)                                                              \
    do {                                                                        \
        unsigned short* bhi = sA + (p_) * ABUF;                                 \
        unsigned short* blo = bhi + 64 * SPAD;                                  \
        if (presplit) {                                                         \
            int row = t >> 4, c = t & 15;                                       \
            ((uint4*)bhi)[row * 17 + c] = ph0;                                  \
            ((uint4*)blo)[row * 17 + c] = pl0;                                  \
            ((uint4*)bhi)[(row + 32) * 17 + c] = ph1;                           \
            ((uint4*)blo)[(row + 32) * 17 + c] = pl1;                           \
        } else {                                                                \
            int row = t >> 5, c4 = t & 31;                                      \
            ushort4 h, l;                                                       \
            split_bf16(pv0.x, h.x, l.x); split_bf16(pv0.y, h.y, l.y);           \
            split_bf16(pv0.z, h.z, l.z); split_bf16(pv0.w, h.w, l.w);           \
            ((ushort4*)bhi)[row * 34 + c4] = h;                                 \
            ((ushort4*)blo)[row * 34 + c4] = l;                                 \
            split_bf16(pv1.x, h.x, l.x); split_bf16(pv1.y, h.y, l.y);           \
            split_bf16(pv1.z, h.z, l.z); split_bf16(pv1.w, h.w, l.w);           \
            ((ushort4*)bhi)[(row + 16) * 34 + c4] = h;                          \
            ((ushort4*)blo)[(row + 16) * 34 + c4] = l;                          \
            split_bf16(pv2.x, h.x, l.x); split_bf16(pv2.y, h.y, l.y);           \
            split_bf16(pv2.z, h.z, l.z); split_bf16(pv2.w, h.w, l.w);           \
            ((ushort4*)bhi)[(row + 32) * 34 + c4] = h;                          \
            ((ushort4*)blo)[(row + 32) * 34 + c4] = l;                          \
            split_bf16(pv3.x, h.x, l.x); split_bf16(pv3.y, h.y, l.y);           \
            split_bf16(pv3.z, h.z, l.z); split_bf16(pv3.w, h.w, l.w);           \
            ((ushort4*)bhi)[(row + 48) * 34 + c4] = h;                          \
            ((ushort4*)blo)[(row + 48) * 34 + c4] = l;                          \
        }                                                                       \
    } while (0)

    const int tile0 = blockIdx.x;
    if (tile0 < NTILES) {
        LOADA(tile0);
        STOREA(0);
    }
    __syncthreads();

    int p = 0;
    for (int tile = tile0; tile < NTILES; tile += gridDim.x) {
        const int nxt = tile + gridDim.x;
        if (nxt < NTILES) LOADA(nxt);

        const unsigned aOff = p * ABUF * 2;
        float acc[2][4][4];
#pragma unroll
        for (int mi = 0; mi < 2; mi++)
#pragma unroll
            for (int ni = 0; ni < 4; ni++)
#pragma unroll
                for (int j = 0; j < 4; j++) acc[mi][ni][j] = 0.f;

#pragma unroll
        for (int k0 = 0; k0 < 128; k0 += 16) {
            unsigned a_hi[2][4], a_lo[2][4];
#pragma unroll
            for (int mi = 0; mi < 2; mi++) {
                unsigned off = mi * 16 * SPAD * 2 + k0 * 2 + aOff;
                ldsm_x4(a_hi[mi][0], a_hi[mi][1], a_hi[mi][2], a_hi[mi][3], aHiBase0 + off);
                ldsm_x4(a_lo[mi][0], a_lo[mi][1], a_lo[mi][2], a_lo[mi][3], aLoBase0 + off);
            }
            unsigned b_hi[4][2], b_lo[4][2];
#pragma unroll
            for (int nj = 0; nj < 2; nj++) {
                unsigned off = nj * 16 * SPAD * 2 + k0 * 2;
                ldsm_x4(b_hi[2 * nj][0], b_hi[2 * nj][1],
                        b_hi[2 * nj + 1][0], b_hi[2 * nj + 1][1], bHiBase + off);
                ldsm_x4(b_lo[2 * nj][0], b_lo[2 * nj][1],
                        b_lo[2 * nj + 1][0], b_lo[2 * nj + 1][1], bLoBase + off);
            }
#pragma unroll
            for (int mi = 0; mi < 2; mi++)
#pragma unroll
                for (int ni = 0; ni < 4; ni++) {
                    MMA_B16(acc[mi][ni], a_hi[mi], b_hi[ni]);
                    MMA_B16(acc[mi][ni], a_hi[mi], b_lo[ni]);
                    MMA_B16(acc[mi][ni], a_lo[mi], b_hi[ni]);
                }
        }

        const int r0 = tile * 64;
#pragma unroll
        for (int mi = 0; mi < 2; mi++) {
            int r = r0 + warpM * 32 + mi * 16 + g;
#pragma unroll
            for (int ni = 0; ni < 4; ni++) {
                int c = warpN * 32 + ni * 8 + q * 2;
                if (r < N_NODES)
                    *(float2*)&C[r * DIM + c] = make_float2(acc[mi][ni][0], acc[mi][ni][1]);
                if (r + 8 < N_NODES)
                    *(float2*)&C[(r + 8) * DIM + c] = make_float2(acc[mi][ni][2], acc[mi][ni][3]);
            }
        }

        if (nxt < NTILES) STOREA(p ^ 1);
        __syncthreads();
        p ^= 1;
    }
#undef LOADA
#undef STOREA
}

// ---------------- GATv2 edge aggregation: one warp per dst node ------------
// Softmax without max subtraction (logits O(±7), fp32-safe).
// att*lrelu(s) = s * (s>0 ? att : 0.2*att).  4-edge unroll (MLP=4).
__device__ __forceinline__ float head_logit(float4 xv, float4 xrv,
                                            float4 av, float4 avn) {
    float s0 = xv.x + xrv.x;
    float s1 = xv.y + xrv.y;
    float s2 = xv.z + xrv.z;
    float s3 = xv.w + xrv.w;
    float p = s0 * (s0 > 0.f ? av.x : avn.x);
    p = fmaf(s1, (s1 > 0.f ? av.y : avn.y), p);
    p = fmaf(s2, (s2 > 0.f ? av.z : avn.z), p);
    p = fmaf(s3, (s3 > 0.f ? av.w : avn.w), p);
    return p;
}

// mode 0: concat + relu, output fused into bf16 hi/lo split (layer-2 A operand)
// mode 1: head-mean + relu, fp32 to `out`
__global__ __launch_bounds__(256)
void gat_edge(const float* __restrict__ xl, const float* __restrict__ xr,
              const float* __restrict__ att, const float* __restrict__ bias,
              float* __restrict__ out, int mode) {
    int warp = (blockIdx.x * blockDim.x + threadIdx.x) >> 5;
    if (warp >= N_NODES) return;
    const int lane = threadIdx.x & 31;
    const int node = warp;

    const float4 xrv = ((const float4*)xr)[node * 32 + lane];
    const float4 av  = ((const float4*)att)[lane];
    const float4 avn = make_float4(0.2f * av.x, 0.2f * av.y, 0.2f * av.z, 0.2f * av.w);

    const int beg = g_off[node];
    const int end = g_off[node + 1];

    float  dsum = 0.f;
    float4 acc = make_float4(0.f, 0.f, 0.f, 0.f);

    int e = beg;
    for (; e + 4 <= end; e += 4) {
        int s0 = g_src[e], s1 = g_src[e + 1], s2 = g_src[e + 2], s3 = g_src[e + 3];
        float4 x0 = ((const float4*)xl)[s0 * 32 + lane];
        float4 x1 = ((const float4*)xl)[s1 * 32 + lane];
        float4 x2 = ((const float4*)xl)[s2 * 32 + lane];
        float4 x3 = ((const float4*)xl)[s3 * 32 + lane];
        float p0 = head_logit(x0, xrv, av, avn);
        float p1 = head_logit(x1, xrv, av, avn);
        float p2 = head_logit(x2, xrv, av, avn);
        float p3 = head_logit(x3, xrv, av, avn);
        p0 += __shfl_xor_sync(0xffffffffu, p0, 1);
        p1 += __shfl_xor_sync(0xffffffffu, p1, 1);
        p2 += __shfl_xor_sync(0xffffffffu, p2, 1);
        p3 += __shfl_xor_sync(0xffffffffu, p3, 1);
        p0 += __shfl_xor_sync(0xffffffffu, p0, 2);
        p1 += __shfl_xor_sync(0xffffffffu, p1, 2);
        p2 += __shfl_xor_sync(0xffffffffu, p2, 2);
        p3 += __shfl_xor_sync(0xffffffffu, p3, 2);
        p0 += __shfl_xor_sync(0xffffffffu, p0, 4);
        p1 += __shfl_xor_sync(0xffffffffu, p1, 4);
        p2 += __shfl_xor_sync(0xffffffffu, p2, 4);
        p3 += __shfl_xor_sync(0xffffffffu, p3, 4);

        float w0 = __expf(p0);
        float w1 = __expf(p1);
        float w2 = __expf(p2);
        float w3 = __expf(p3);
        dsum += (w0 + w1) + (w2 + w3);
        acc.x += w0 * x0.x + w1 * x1.x + w2 * x2.x + w3 * x3.x;
        acc.y += w0 * x0.y + w1 * x1.y + w2 * x2.y + w3 * x3.y;
        acc.z += w0 * x0.z + w1 * x1.z + w2 * x2.z + w3 * x3.z;
        acc.w += w0 * x0.w + w1 * x1.w + w2 * x2.w + w3 * x3.w;
    }
    for (; e + 2 <= end; e += 2) {
        int s0 = g_src[e], s1 = g_src[e + 1];
        float4 x0 = ((const float4*)xl)[s0 * 32 + lane];
        float4 x1 = ((const float4*)xl)[s1 * 32 + lane];
        float p0 = head_logit(x0, xrv, av, avn);
        float p1 = head_logit(x1, xrv, av, avn);
        p0 += __shfl_xor_sync(0xffffffffu, p0, 1);
        p1 += __shfl_xor_sync(0xffffffffu, p1, 1);
        p0 += __shfl_xor_sync(0xffffffffu, p0, 2);
        p1 += __shfl_xor_sync(0xffffffffu, p1, 2);
        p0 += __shfl_xor_sync(0xffffffffu, p0, 4);
        p1 += __shfl_xor_sync(0xffffffffu, p1, 4);
        float w0 = __expf(p0);
        float w1 = __expf(p1);
        dsum += w0 + w1;
        acc.x += w0 * x0.x + w1 * x1.x;
        acc.y += w0 * x0.y + w1 * x1.y;
        acc.z += w0 * x0.z + w1 * x1.z;
        acc.w += w0 * x0.w + w1 * x1.w;
    }
    if (e < end) {
        int s = g_src[e];
        float4 xv = ((const float4*)xl)[s * 32 + lane];
        float p = head_logit(xv, xrv, av, avn);
        p += __shfl_xor_sync(0xffffffffu, p, 1);
        p += __shfl_xor_sync(0xffffffffu, p, 2);
        p += __shfl_xor_sync(0xffffffffu, p, 4);
        float w = __expf(p);
        dsum += w;
        acc.x += w * xv.x;
        acc.y += w * xv.y;
        acc.z += w * xv.z;
        acc.w += w * xv.w;
    }

    float inv = 1.f / dsum;
    if (mode == 0) {
        float4 b = ((const float4*)bias)[lane];
        float o0 = fmaxf(acc.x * inv + b.x, 0.f);
        float o1 = fmaxf(acc.y * inv + b.y, 0.f);
        float o2 = fmaxf(acc.z * inv + b.z, 0.f);
        float o3 = fmaxf(acc.w * inv + b.w, 0.f);
        ushort4 hv, lv;
        split_bf16(o0, hv.x, lv.x);
        split_bf16(o1, hv.y, lv.y);
        split_bf16(o2, hv.z, lv.z);
        split_bf16(o3, hv.w, lv.w);
        ((ushort4*)g_Ahi)[node * 32 + lane] = hv;
        ((ushort4*)g_Alo)[node * 32 + lane] = lv;
    } else {
        float vx = acc.x * inv, vy = acc.y * inv, vz = acc.z * inv, vw = acc.w * inv;
        vx += __shfl_xor_sync(0xffffffffu, vx, 8);
        vx += __shfl_xor_sync(0xffffffffu, vx, 16);
        vy += __shfl_xor_sync(0xffffffffu, vy, 8);
        vy += __shfl_xor_sync(0xffffffffu, vy, 16);
        vz += __shfl_xor_sync(0xffffffffu, vz, 8);
        vz += __shfl_xor_sync(0xffffffffu, vz, 16);
        vw += __shfl_xor_sync(0xffffffffu, vw, 8);
        vw += __shfl_xor_sync(0xffffffffu, vw, 16);
        if (lane < 8) {
            float4 b = ((const float4*)bias)[lane];
            float4 o;
            o.x = fmaxf(vx * 0.25f + b.x, 0.f);
            o.y = fmaxf(vy * 0.25f + b.y, 0.f);
            o.z = fmaxf(vz * 0.25f + b.z, 0.f);
            o.w = fmaxf(vw * 0.25f + b.w, 0.f);
            ((float4*)out)[node * 8 + lane] = o;
        }
    }
}

// ---------------- launch ---------------------------------------------------
// Graph fork-join: CSR build (memset->hist->scan->scatter) on a side stream,
// concurrent with prep_W -> gemm1 on the capture stream; joined before
// gat_edge1.
extern "C" void kernel_launch(void* const* d_in, const int* in_sizes, int n_in,
                              void* d_out, int out_size) {
    const float* x    = (const float*)d_in[0];
    const int*   ei   = (const int*)d_in[1];
    const float* Wl1  = (const float*)d_in[2];
    const float* Wr1  = (const float*)d_in[3];
    const float* att1 = (const float*)d_in[4];
    const float* b1   = (const float*)d_in[5];
    const float* Wl2  = (const float*)d_in[6];
    const float* Wr2  = (const float*)d_in[7];
    const float* att2 = (const float*)d_in[8];
    const float* b2   = (const float*)d_in[9];
    float* out = (float*)d_out;

    void* p_cnt = nullptr;
    float *xl = nullptr, *xr = nullptr;
    cudaGetSymbolAddress(&p_cnt, g_cnt);
    cudaGetSymbolAddress((void**)&xl, g_xl);
    cudaGetSymbolAddress((void**)&xr, g_xr);

    static cudaStream_t side = nullptr;
    static cudaEvent_t evFork = nullptr, evJoin = nullptr;
    if (side == nullptr) {
        cudaStreamCreateWithFlags(&side, cudaStreamNonBlocking);
        cudaEventCreateWithFlags(&evFork, cudaEventDisableTiming);
        cudaEventCreateWithFlags(&evJoin, cudaEventDisableTiming);
    }

    const int SMEM = (4 * 128 * SPAD + 2 * ABUF) * 2;  // 208896 bytes
    cudaFuncSetAttribute(gemm_tc, cudaFuncAttributeMaxDynamicSharedMemorySize, SMEM);

    // ---- fork: CSR build on side stream ----
    cudaEventRecord(evFork, 0);
    cudaStreamWaitEvent(side, evFork, 0);
    cudaMemsetAsync(p_cnt, 0, N_NODES * sizeof(int), side);
    hist_kernel<<<(N_EDGES + 2047) / 2048, 256, 0, side>>>(ei);
    scan_kernel<<<1, 1024, 0, side>>>();
    scatter_kernel<<<(E_TOT + 2047) / 2048, 256, 0, side>>>(ei);
    cudaEventRecord(evJoin, side);

    // ---- main: weights + layer-1 GEMM (independent of CSR) ----
    prep_W<<<(4 * 128 * SPAD) / 256, 256>>>(Wl1, Wr1, Wl2, Wr2);
    gemm_tc<<<148, 512, SMEM>>>(x, 0, 0, xl, xr);

    // ---- join, then edge phases ----
    cudaStreamWaitEvent(0, evJoin, 0);
    gat_edge<<<(N_NODES * 32 + 255) / 256, 256>>>(xl, xr, att1, b1, nullptr, 0);
    gemm_tc<<<148, 512, SMEM>>>(nullptr, 2, 1, xl, xr);
    gat_edge<<<(N_NODES * 32 + 255) / 256, 256>>>(xl, xr, att2, b2, out, 1);
}